// round 15
// baseline (speedup 1.0000x reference)
#include <cuda_runtime.h>
#include <cuda_fp16.h>
#include <math.h>
#include <stdint.h>

#define NN 100000
#define NE 1600000
#define BKT_SHIFT 7   // 128 slots per node; P(Poisson(16) >= 128) ~ 1e-60

// PDL: block until predecessor-grid memory is visible / release dependents
#define GDC_WAIT()   asm volatile("griddepcontrol.wait;" ::: "memory")
#define GDC_LAUNCH() asm volatile("griddepcontrol.launch_dependents;" ::: "memory")

// ---------------- scratch (device globals: no allocation allowed) -------------
// NOTE: g_cnt must be zero on entry to bucket_k. Zero-initialized at module
// load; final_k re-zeroes it each call (invariant across graph replays).
__device__ __half g_uh[NN * 64];        // layer-1 u = (x W1) * dis, fp16
__device__ __half g_uh2[NN * 64];       // layer-2 u = (h W2) * dis, fp16
__device__ float  g_u3[NN];             // layer-3 scalar pre-aggregation
__device__ int    g_cnt[NN];            // in-degree (without self loop)
__device__ int    g_csr[NN << BKT_SHIFT]; // fixed-stride buckets of src ids

// ---------------- helpers ------------------------------------------------------
__device__ __forceinline__ uint32_t smem_u32(const void* p) {
    uint32_t a;
    asm("{ .reg .u64 t; cvta.to.shared.u64 t, %1; cvt.u32.u64 %0, t; }" : "=r"(a) : "l"(p));
    return a;
}
#define SWZ128(o) ((o) ^ (((o) >> 3) & 0x70))

__device__ __forceinline__ void ldsm_x4(uint32_t a, uint32_t& r0, uint32_t& r1,
                                        uint32_t& r2, uint32_t& r3) {
    asm volatile("ldmatrix.sync.aligned.m8n8.x4.shared.b16 {%0,%1,%2,%3}, [%4];"
                 : "=r"(r0), "=r"(r1), "=r"(r2), "=r"(r3) : "r"(a));
}
__device__ __forceinline__ void mma_f16(float* d, const uint32_t* a, uint32_t b0, uint32_t b1) {
    asm volatile("mma.sync.aligned.m16n8k16.row.col.f32.f16.f16.f32 "
                 "{%0,%1,%2,%3}, {%4,%5,%6,%7}, {%8,%9}, {%0,%1,%2,%3};"
                 : "+f"(d[0]), "+f"(d[1]), "+f"(d[2]), "+f"(d[3])
                 : "r"(a[0]), "r"(a[1]), "r"(a[2]), "r"(a[3]), "r"(b0), "r"(b1));
}

// per-block dtype vote: int64 edge values < 2^31 -> every odd 32-bit word of
// the first 256 entries is 0; int32 -> those words are node ids (never all 0).
__device__ __forceinline__ int detect64_block(const int* ei32) {
    int bad = (ei32[2 * (threadIdx.x & 255) + 1] != 0) ? 1 : 0;
    int any = __syncthreads_or(bad);
    return any ? 0 : 1;
}

__device__ __forceinline__ float dis_of(int d) {
    return rsqrtf((float)g_cnt[d] + 1.0f);
}

// ---------------- structure build: one kernel, no scan -------------------------
__global__ void bucket_k(const void* ei) {
    GDC_WAIT();
    int is64 = detect64_block((const int*)ei);
    int e = blockIdx.x * blockDim.x + threadIdx.x;
    if (e < NE) {
        int s, d;
        if (is64) {
            const long long* p = (const long long*)ei;
            s = (int)p[e];
            d = (int)p[NE + e];
        } else {
            const int* p = (const int*)ei;
            s = p[e];
            d = p[NE + e];
        }
        int r = atomicAdd(&g_cnt[d], 1);
        g_csr[(d << BKT_SHIFT) + r] = s;
    }
    GDC_LAUNCH();
}

// ---------------- fp16 MMA GEMM (layer 1) --------------------------------------
// g_uh[row, 0:64] = fp16( (x[row, 0:128] @ W1) * dis[row] )
// 256 rows/CTA, 8 warps x 32 rows. K in 64-chunks, SW128-swizzled smem.
// GDC_WAIT deferred: mainloop reads only x/W1 (harness inputs), so it overlaps
// bucket_k under PDL; only dis (g_cnt) needs the wait. GDC_LAUNCH after wait
// preserves transitive visibility of bucket_k's stores for dependents.
__global__ void __launch_bounds__(256)
gemm1_k(const float* __restrict__ Ain, const float* __restrict__ W) {
    extern __shared__ char dsm[];
    uint32_t sb0 = smem_u32(dsm);
    uint32_t sb = (sb0 + 1023) & ~1023u;
    char* p = dsm + (sb - sb0);
    const uint32_t AH = sb, BH = sb + 32768;
    char* pAH = p;
    char* pBH = p + 32768;

    const int tid = threadIdx.x, wid = tid >> 5, lane = tid & 31;
    const int row0 = blockIdx.x * 256;
    const int g = lane >> 2, tig = lane & 3;

    float acc[2][8][4];
    #pragma unroll
    for (int i = 0; i < 2; i++)
        #pragma unroll
        for (int j = 0; j < 8; j++)
            #pragma unroll
            for (int r = 0; r < 4; r++) acc[i][j][r] = 0.f;

    for (int ch = 0; ch < 2; ch++) {
        __syncthreads();

        #pragma unroll
        for (int it = tid; it < 4096; it += 256) {   // 256 rows * 16 float4
            int r = it >> 4, c4 = it & 15;
            int row = row0 + r;
            float4 v = make_float4(0.f, 0.f, 0.f, 0.f);
            if (row < NN) v = ((const float4*)Ain)[(size_t)row * 32 + ch * 16 + c4];
            __half2 h01 = __floats2half2_rn(v.x, v.y);
            __half2 h23 = __floats2half2_rn(v.z, v.w);
            uint32_t so = SWZ128((uint32_t)(r * 128 + c4 * 8));
            *(uint2*)(pAH + so) = make_uint2(*(uint32_t*)&h01, *(uint32_t*)&h23);
        }
        #pragma unroll
        for (int it = tid; it < 4096; it += 256) {   // 64 k * 64 n
            int kloc = it >> 6, n = it & 63;
            float w = W[(size_t)(ch * 64 + kloc) * 64 + n];
            uint32_t so = SWZ128((uint32_t)(n * 128 + kloc * 2));
            *(__half*)(pBH + so) = __float2half_rn(w);
        }
        __syncthreads();

        #pragma unroll
        for (int ks = 0; ks < 4; ks++) {
            uint32_t ar   = (uint32_t)(wid * 32 + (lane & 15));
            uint32_t akb  = (uint32_t)(ks * 32 + ((lane >> 4) << 4));
            uint32_t aof0 = SWZ128(ar * 128 + akb);
            uint32_t aof1 = SWZ128((ar + 16) * 128 + akb);
            uint32_t ah0[4], ah1[4];
            ldsm_x4(AH + aof0, ah0[0], ah0[1], ah0[2], ah0[3]);
            ldsm_x4(AH + aof1, ah1[0], ah1[1], ah1[2], ah1[3]);

            uint32_t bkb = (uint32_t)(ks * 32 + (((lane >> 3) & 1) << 4));
            #pragma unroll
            for (int jj = 0; jj < 4; jj++) {
                uint32_t bn = (uint32_t)(jj * 16 + (lane & 7) + ((lane >> 4) << 3));
                uint32_t bof = SWZ128(bn * 128 + bkb);
                uint32_t bh[4];
                ldsm_x4(BH + bof, bh[0], bh[1], bh[2], bh[3]);
                mma_f16(acc[0][2 * jj],     ah0, bh[0], bh[1]);
                mma_f16(acc[1][2 * jj],     ah1, bh[0], bh[1]);
                mma_f16(acc[0][2 * jj + 1], ah0, bh[2], bh[3]);
                mma_f16(acc[1][2 * jj + 1], ah1, bh[2], bh[3]);
            }
        }
    }

    GDC_WAIT();  // bucket_k results (g_cnt) needed only from here on

    #pragma unroll
    for (int G = 0; G < 2; G++) {
        int r_lo = row0 + wid * 32 + G * 16 + g;
        int r_hi = r_lo + 8;
        float s_lo = (r_lo < NN) ? dis_of(r_lo) : 0.f;
        float s_hi = (r_hi < NN) ? dis_of(r_hi) : 0.f;
        #pragma unroll
        for (int j = 0; j < 8; j++) {
            int col = j * 8 + tig * 2;
            if (r_lo < NN)
                *(__half2*)&g_uh[(size_t)r_lo * 64 + col] =
                    __floats2half2_rn(acc[G][j][0] * s_lo, acc[G][j][1] * s_lo);
            if (r_hi < NN)
                *(__half2*)&g_uh[(size_t)r_hi * 64 + col] =
                    __floats2half2_rn(acc[G][j][2] * s_hi, acc[G][j][3] * s_hi);
        }
    }
    GDC_LAUNCH();
}

// ---------------- fused agg1 + gemm2 (64 nodes/block) ---------------------------
// Phase 1: 4 iterations x 16 nodes of HADD2 gather+bias+relu -> h in smem
// (64 rows x 128B, SW128). Phase 2: u2 = dis * (h @ W2) via MMA -> g_uh2.
// W2 staged once per 64 nodes (R13's failure was staging per 16).
__global__ void __launch_bounds__(256) agg1gemm2_k(const float* __restrict__ b,
                                                   const float* __restrict__ W2) {
    GDC_WAIT();
    __shared__ __align__(1024) char sW[8192];   // W2 [n][k] fp16, SW128
    __shared__ __align__(1024) char sH[8192];   // h [64 rows][128B] fp16, SW128
    const int tid = threadIdx.x;
    const int grp = tid >> 4, sub = tid & 15, wid = tid >> 5, lane = tid & 31;
    const int d0 = blockIdx.x * 64;

    // stage W2 (fp32 gmem -> fp16 smem, swizzled)
    #pragma unroll
    for (int it = tid; it < 4096; it += 256) {
        int kloc = it >> 6, n = it & 63;
        float w = W2[(size_t)kloc * 64 + n];
        *(__half*)(sW + SWZ128((uint32_t)(n * 128 + kloc * 2))) = __float2half_rn(w);
    }

    // phase 1: gather + bias + relu, 16 nodes per iteration
    const uint2* U = (const uint2*)g_uh;
    float4 bb = ((const float4*)b)[sub];
    #pragma unroll
    for (int itr = 0; itr < 4; itr++) {
        int rloc = itr * 16 + grp;
        int d = d0 + rloc;
        __half2 p0 = __float2half2_rn(0.f), p1 = __float2half2_rn(0.f);
        if (d < NN) {
            uint2 raw = U[(size_t)d * 16 + sub];  // self-loop term
            __half2 a0e = *(__half2*)&raw.x;
            __half2 a1e = *(__half2*)&raw.y;
            __half2 a0o = __float2half2_rn(0.f);
            __half2 a1o = __float2half2_rn(0.f);
            int n = g_cnt[d];
            const int* bkt = &g_csr[d << BKT_SHIFT];
            int e = 0;
            #pragma unroll 2
            for (; e + 1 < n; e += 2) {
                int s0 = bkt[e], s1 = bkt[e + 1];
                uint2 r0 = U[(size_t)s0 * 16 + sub];
                uint2 r1 = U[(size_t)s1 * 16 + sub];
                a0e = __hadd2(a0e, *(__half2*)&r0.x);
                a1e = __hadd2(a1e, *(__half2*)&r0.y);
                a0o = __hadd2(a0o, *(__half2*)&r1.x);
                a1o = __hadd2(a1o, *(__half2*)&r1.y);
            }
            if (e < n) {
                uint2 r0 = U[(size_t)bkt[e] * 16 + sub];
                a0o = __hadd2(a0o, *(__half2*)&r0.x);
                a1o = __hadd2(a1o, *(__half2*)&r0.y);
            }
            float2 f0e = __half22float2(a0e), f0o = __half22float2(a0o);
            float2 f1e = __half22float2(a1e), f1o = __half22float2(a1o);
            float sc = rsqrtf((float)n + 1.0f);
            p0 = __floats2half2_rn(fmaxf(sc * (f0e.x + f0o.x) + bb.x, 0.f),
                                   fmaxf(sc * (f0e.y + f0o.y) + bb.y, 0.f));
            p1 = __floats2half2_rn(fmaxf(sc * (f1e.x + f1o.x) + bb.z, 0.f),
                                   fmaxf(sc * (f1e.y + f1o.y) + bb.w, 0.f));
        }
        *(uint2*)(sH + SWZ128((uint32_t)(rloc * 128 + sub * 8))) =
            make_uint2(*(uint32_t*)&p0, *(uint32_t*)&p1);
    }
    __syncthreads();

    // phase 2: 8 warps; warp w -> rows (w&3)*16..+15, cols (w>>2)*32..+31
    uint32_t sHa = smem_u32(sH), sWa = smem_u32(sW);
    const int rbase = (wid & 3) * 16;
    const int cbase = (wid >> 2) * 32;
    float acc[2][2][4];  // [jjp][half][4]
    #pragma unroll
    for (int i = 0; i < 2; i++)
        #pragma unroll
        for (int j = 0; j < 2; j++)
            #pragma unroll
            for (int r = 0; r < 4; r++) acc[i][j][r] = 0.f;

    #pragma unroll
    for (int ks = 0; ks < 4; ks++) {
        uint32_t ar  = (uint32_t)(rbase + (lane & 15));
        uint32_t akb = (uint32_t)(ks * 32 + ((lane >> 4) << 4));
        uint32_t a[4];
        ldsm_x4(sHa + SWZ128(ar * 128 + akb), a[0], a[1], a[2], a[3]);
        uint32_t bkb = (uint32_t)(ks * 32 + (((lane >> 3) & 1) << 4));
        #pragma unroll
        for (int jjp = 0; jjp < 2; jjp++) {
            uint32_t bn = (uint32_t)(cbase + jjp * 16 + (lane & 7) + ((lane >> 4) << 3));
            uint32_t bh[4];
            ldsm_x4(sWa + SWZ128(bn * 128 + bkb), bh[0], bh[1], bh[2], bh[3]);
            mma_f16(acc[jjp][0], a, bh[0], bh[1]);
            mma_f16(acc[jjp][1], a, bh[2], bh[3]);
        }
    }

    // epilogue: scale rows by dis, store fp16 u2
    int g = lane >> 2, tig = lane & 3;
    int r_lo = d0 + rbase + g, r_hi = r_lo + 8;
    float s_lo = (r_lo < NN) ? dis_of(r_lo) : 0.f;
    float s_hi = (r_hi < NN) ? dis_of(r_hi) : 0.f;
    #pragma unroll
    for (int jjp = 0; jjp < 2; jjp++)
        #pragma unroll
        for (int half = 0; half < 2; half++) {
            int col = cbase + jjp * 16 + half * 8 + tig * 2;
            if (r_lo < NN)
                *(__half2*)&g_uh2[(size_t)r_lo * 64 + col] =
                    __floats2half2_rn(acc[jjp][half][0] * s_lo, acc[jjp][half][1] * s_lo);
            if (r_hi < NN)
                *(__half2*)&g_uh2[(size_t)r_hi * 64 + col] =
                    __floats2half2_rn(acc[jjp][half][2] * s_hi, acc[jjp][half][3] * s_hi);
        }
    GDC_LAUNCH();
}

// ---------------- agg2: gather u2 (HADD2) + bias + relu + fused W3 dot ---------
__global__ void agg2_k(const float* __restrict__ b, const float* __restrict__ W3) {
    GDC_WAIT();
    int tid = threadIdx.x;
    int grp = tid >> 4, sub = tid & 15;
    int d = blockIdx.x * 16 + grp;

    const uint2* U = (const uint2*)g_uh2;
    uint2 raw = U[(size_t)d * 16 + sub];  // self-loop term
    __half2 a0e = *(__half2*)&raw.x;
    __half2 a1e = *(__half2*)&raw.y;
    __half2 a0o = __float2half2_rn(0.f);
    __half2 a1o = __float2half2_rn(0.f);
    int n = g_cnt[d];
    const int* bkt = &g_csr[d << BKT_SHIFT];
    int e = 0;
    #pragma unroll 2
    for (; e + 1 < n; e += 2) {
        int s0 = bkt[e], s1 = bkt[e + 1];
        uint2 r0 = U[(size_t)s0 * 16 + sub];
        uint2 r1 = U[(size_t)s1 * 16 + sub];
        a0e = __hadd2(a0e, *(__half2*)&r0.x);
        a1e = __hadd2(a1e, *(__half2*)&r0.y);
        a0o = __hadd2(a0o, *(__half2*)&r1.x);
        a1o = __hadd2(a1o, *(__half2*)&r1.y);
    }
    if (e < n) {
        uint2 r0 = U[(size_t)bkt[e] * 16 + sub];
        a0o = __hadd2(a0o, *(__half2*)&r0.x);
        a1o = __hadd2(a1o, *(__half2*)&r0.y);
    }
    float2 f0e = __half22float2(a0e), f0o = __half22float2(a0o);
    float2 f1e = __half22float2(a1e), f1o = __half22float2(a1o);
    float sc = rsqrtf((float)n + 1.0f);
    float4 bb = ((const float4*)b)[sub];
    float4 o;
    o.x = fmaxf(sc * (f0e.x + f0o.x) + bb.x, 0.f);
    o.y = fmaxf(sc * (f0e.y + f0o.y) + bb.y, 0.f);
    o.z = fmaxf(sc * (f1e.x + f1o.x) + bb.z, 0.f);
    o.w = fmaxf(sc * (f1e.y + f1o.y) + bb.w, 0.f);
    float4 w3 = ((const float4*)W3)[sub];
    float dot = o.x * w3.x + o.y * w3.y + o.z * w3.z + o.w * w3.w;
    #pragma unroll
    for (int off = 8; off; off >>= 1) dot += __shfl_xor_sync(0xffffffffu, dot, off);
    if (sub == 0) g_u3[d] = dot * sc;
    GDC_LAUNCH();
}

// ---------------- final: out = sigmoid(dis*(sum u3 + u3[d]) + b3) -------------
// Also re-zeroes g_cnt for the next graph replay (invariant: zero on entry).
__global__ void final_k(const float* __restrict__ b3, float* __restrict__ out) {
    GDC_WAIT();
    int d = blockIdx.x * blockDim.x + threadIdx.x;
    if (d < NN) {
        int n = g_cnt[d];
        const int* bkt = &g_csr[d << BKT_SHIFT];
        float s = g_u3[d];
        #pragma unroll 4
        for (int e = 0; e < n; e++) s += g_u3[bkt[e]];
        float z = rsqrtf((float)n + 1.0f) * s + b3[0];
        out[d] = 1.0f / (1.0f + expf(-z));
        g_cnt[d] = 0;
    }
}

// ---------------- launch -------------------------------------------------------
template <typename F, typename... A>
static inline void pdl(F* f, dim3 grid, dim3 blk, size_t smem, A... args) {
    cudaLaunchConfig_t cfg = {};
    cfg.gridDim = grid;
    cfg.blockDim = blk;
    cfg.dynamicSmemBytes = smem;
    cfg.stream = 0;
    cudaLaunchAttribute at[1];
    at[0].id = cudaLaunchAttributeProgrammaticStreamSerialization;
    at[0].val.programmaticStreamSerializationAllowed = 1;
    cfg.attrs = at;
    cfg.numAttrs = 1;
    cudaLaunchKernelEx(&cfg, f, args...);
}

extern "C" void kernel_launch(void* const* d_in, const int* in_sizes, int n_in,
                              void* d_out, int out_size) {
    const float* x  = (const float*)d_in[0];
    const float* W1 = (const float*)d_in[1];
    const float* b1 = (const float*)d_in[2];
    const float* W2 = (const float*)d_in[3];
    const float* b2 = (const float*)d_in[4];
    const float* W3 = (const float*)d_in[5];
    const float* b3 = (const float*)d_in[6];
    const void*  ei = d_in[7];
    float* out = (float*)d_out;

    const int SMEM = 1024 + 32768 + 8192;  // gemm1: pad + A + B = 41984
    cudaFuncSetAttribute(gemm1_k, cudaFuncAttributeMaxDynamicSharedMemorySize, SMEM);

    // structure: one kernel (fixed-stride buckets, no scan)
    pdl(bucket_k, dim3((NE + 255) / 256), dim3(256), 0, ei);
    // layer-1 GEMM (mainloop overlaps bucket_k via deferred GDC_WAIT)
    pdl(gemm1_k, dim3((NN + 255) / 256), dim3(256), SMEM, x, W1);
    // fused layer-1 aggregate + layer-2 GEMM (64 nodes/block)
    pdl(agg1gemm2_k, dim3((NN + 63) / 64), dim3(256), 0, b1, W2);
    // layer-2 aggregate + fused layer-3 dot
    pdl(agg2_k, dim3(NN / 16), dim3(256), 0, b2, W3);
    // final
    pdl(final_k, dim3((NN + 255) / 256), dim3(256), 0, b3, out);
}

// round 16
// speedup vs baseline: 1.0294x; 1.0294x over previous
#include <cuda_runtime.h>
#include <cuda_fp16.h>
#include <math.h>
#include <stdint.h>

#define NN 100000
#define NE 1600000
#define BKT_SHIFT 7   // 128 slots per node; P(Poisson(16) >= 128) ~ 1e-60

// PDL: block until all predecessor-grid memory is visible / release dependents
#define GDC_WAIT()   asm volatile("griddepcontrol.wait;" ::: "memory")
#define GDC_LAUNCH() asm volatile("griddepcontrol.launch_dependents;" ::: "memory")

// ---------------- scratch (device globals: no allocation allowed) -------------
// NOTE: g_cnt must be zero on entry to bucket_k. It is zero-initialized at
// module load, and final_k (the last kernel of every call) re-zeroes it,
// preserving the invariant across graph replays.
__device__ __half g_uh[NN * 64];        // u = (H @ W) * dis, fp16
__device__ __half g_h16[NN * 64];       // layer-1 output after agg+bias+relu (fp16)
__device__ float  g_u3[NN];             // layer-3 scalar pre-aggregation
__device__ int    g_cnt[NN];            // in-degree (without self loop)
__device__ int    g_csr[NN << BKT_SHIFT]; // fixed-stride buckets of src ids

// ---------------- helpers ------------------------------------------------------
__device__ __forceinline__ uint32_t smem_u32(const void* p) {
    uint32_t a;
    asm("{ .reg .u64 t; cvta.to.shared.u64 t, %1; cvt.u32.u64 %0, t; }" : "=r"(a) : "l"(p));
    return a;
}
#define SWZ128(o) ((o) ^ (((o) >> 3) & 0x70))

__device__ __forceinline__ void ldsm_x4(uint32_t a, uint32_t& r0, uint32_t& r1,
                                        uint32_t& r2, uint32_t& r3) {
    asm volatile("ldmatrix.sync.aligned.m8n8.x4.shared.b16 {%0,%1,%2,%3}, [%4];"
                 : "=r"(r0), "=r"(r1), "=r"(r2), "=r"(r3) : "r"(a));
}
__device__ __forceinline__ void mma_f16(float* d, const uint32_t* a, uint32_t b0, uint32_t b1) {
    asm volatile("mma.sync.aligned.m16n8k16.row.col.f32.f16.f16.f32 "
                 "{%0,%1,%2,%3}, {%4,%5,%6,%7}, {%8,%9}, {%0,%1,%2,%3};"
                 : "+f"(d[0]), "+f"(d[1]), "+f"(d[2]), "+f"(d[3])
                 : "r"(a[0]), "r"(a[1]), "r"(a[2]), "r"(a[3]), "r"(b0), "r"(b1));
}

// per-block dtype vote: int64 edge values < 2^31 -> every odd 32-bit word of
// the first 256 entries is 0; int32 -> those words are node ids (never all 0).
__device__ __forceinline__ int detect64_block(const int* ei32) {
    int bad = (ei32[2 * (threadIdx.x & 255) + 1] != 0) ? 1 : 0;
    int any = __syncthreads_or(bad);
    return any ? 0 : 1;
}

__device__ __forceinline__ float dis_of(int d) {
    return rsqrtf((float)g_cnt[d] + 1.0f);
}

// ---------------- structure build: one kernel, no scan -------------------------
__global__ void bucket_k(const void* ei) {
    GDC_WAIT();
    int is64 = detect64_block((const int*)ei);
    int e = blockIdx.x * blockDim.x + threadIdx.x;
    if (e < NE) {
        int s, d;
        if (is64) {
            const long long* p = (const long long*)ei;
            s = (int)p[e];
            d = (int)p[NE + e];
        } else {
            const int* p = (const int*)ei;
            s = p[e];
            d = p[NE + e];
        }
        int r = atomicAdd(&g_cnt[d], 1);
        g_csr[(d << BKT_SHIFT) + r] = s;
    }
    GDC_LAUNCH();
}

// ---------------- fp16 MMA GEMM ------------------------------------------------
// g_uh[row, 0:64] = fp16( (A[row, 0:K] @ W[K, 64]) * dis[row] )
// 256 rows/CTA, 8 warps x 32 rows. K staged in 64-chunks, SW128-swizzled smem.
// Single fp16 MMA, fp32 accumulate. FROM_H: A is fp16 g_h16 (exact copy).
template <int KCHUNKS, bool FROM_H>
__global__ void __launch_bounds__(256)
gemm_mma(const float* __restrict__ Ain, const float* __restrict__ W) {
    GDC_WAIT();
    extern __shared__ char dsm[];
    uint32_t sb0 = smem_u32(dsm);
    uint32_t sb = (sb0 + 1023) & ~1023u;
    char* p = dsm + (sb - sb0);
    const uint32_t AH = sb, BH = sb + 32768;
    char* pAH = p;
    char* pBH = p + 32768;

    constexpr int K = KCHUNKS * 64;
    const int tid = threadIdx.x, wid = tid >> 5, lane = tid & 31;
    const int row0 = blockIdx.x * 256;
    const int g = lane >> 2, tig = lane & 3;

    float acc[2][8][4];
    #pragma unroll
    for (int i = 0; i < 2; i++)
        #pragma unroll
        for (int j = 0; j < 8; j++)
            #pragma unroll
            for (int r = 0; r < 4; r++) acc[i][j][r] = 0.f;

    for (int ch = 0; ch < KCHUNKS; ch++) {
        __syncthreads();

        if (!FROM_H) {
            #pragma unroll
            for (int it = tid; it < 4096; it += 256) {   // 256 rows * 16 float4
                int r = it >> 4, c4 = it & 15;
                int row = row0 + r;
                float4 v = make_float4(0.f, 0.f, 0.f, 0.f);
                if (row < NN) v = ((const float4*)Ain)[(size_t)row * (K / 4) + ch * 16 + c4];
                __half2 h01 = __floats2half2_rn(v.x, v.y);
                __half2 h23 = __floats2half2_rn(v.z, v.w);
                uint32_t so = SWZ128((uint32_t)(r * 128 + c4 * 8));
                *(uint2*)(pAH + so) = make_uint2(*(uint32_t*)&h01, *(uint32_t*)&h23);
            }
        } else {
            #pragma unroll
            for (int it = tid; it < 2048; it += 256) {   // 256 rows * 8 uint4
                int r = it >> 3, c8 = it & 7;
                int row = row0 + r;
                uint4 v = make_uint4(0, 0, 0, 0);
                if (row < NN) v = ((const uint4*)g_h16)[(size_t)row * 8 + c8];
                uint32_t so = SWZ128((uint32_t)(r * 128 + c8 * 16));
                *(uint4*)(pAH + so) = v;
            }
        }
        #pragma unroll
        for (int it = tid; it < 4096; it += 256) {   // 64 k * 64 n
            int kloc = it >> 6, n = it & 63;
            float w = W[(size_t)(ch * 64 + kloc) * 64 + n];
            uint32_t so = SWZ128((uint32_t)(n * 128 + kloc * 2));
            *(__half*)(pBH + so) = __float2half_rn(w);
        }
        __syncthreads();

        #pragma unroll
        for (int ks = 0; ks < 4; ks++) {
            uint32_t ar   = (uint32_t)(wid * 32 + (lane & 15));
            uint32_t akb  = (uint32_t)(ks * 32 + ((lane >> 4) << 4));
            uint32_t aof0 = SWZ128(ar * 128 + akb);
            uint32_t aof1 = SWZ128((ar + 16) * 128 + akb);
            uint32_t ah0[4], ah1[4];
            ldsm_x4(AH + aof0, ah0[0], ah0[1], ah0[2], ah0[3]);
            ldsm_x4(AH + aof1, ah1[0], ah1[1], ah1[2], ah1[3]);

            uint32_t bkb = (uint32_t)(ks * 32 + (((lane >> 3) & 1) << 4));
            #pragma unroll
            for (int jj = 0; jj < 4; jj++) {
                uint32_t bn = (uint32_t)(jj * 16 + (lane & 7) + ((lane >> 4) << 3));
                uint32_t bof = SWZ128(bn * 128 + bkb);
                uint32_t bh[4];
                ldsm_x4(BH + bof, bh[0], bh[1], bh[2], bh[3]);
                mma_f16(acc[0][2 * jj],     ah0, bh[0], bh[1]);
                mma_f16(acc[1][2 * jj],     ah1, bh[0], bh[1]);
                mma_f16(acc[0][2 * jj + 1], ah0, bh[2], bh[3]);
                mma_f16(acc[1][2 * jj + 1], ah1, bh[2], bh[3]);
            }
        }
    }

    // ---- epilogue: scale by dis (from cnt), store fp16 ----
    #pragma unroll
    for (int G = 0; G < 2; G++) {
        int r_lo = row0 + wid * 32 + G * 16 + g;
        int r_hi = r_lo + 8;
        float s_lo = (r_lo < NN) ? dis_of(r_lo) : 0.f;
        float s_hi = (r_hi < NN) ? dis_of(r_hi) : 0.f;
        #pragma unroll
        for (int j = 0; j < 8; j++) {
            int col = j * 8 + tig * 2;
            if (r_lo < NN)
                *(__half2*)&g_uh[(size_t)r_lo * 64 + col] =
                    __floats2half2_rn(acc[G][j][0] * s_lo, acc[G][j][1] * s_lo);
            if (r_hi < NN)
                *(__half2*)&g_uh[(size_t)r_hi * 64 + col] =
                    __floats2half2_rn(acc[G][j][2] * s_hi, acc[G][j][3] * s_hi);
        }
    }
    GDC_LAUNCH();
}

// ---------------- aggregate + bias + relu (+ optional fused W3 dot) -----------
// 8 lanes per node, each lane owns 8 cols (uint4 / LDG.128). 32 nodes/block.
// HADD2 accumulation, even/odd dual accumulators combined in fp32.
template <bool FUSE_DOT>
__global__ void agg_relu(const float* __restrict__ b, const float* __restrict__ W3) {
    GDC_WAIT();
    int tid = threadIdx.x;
    int grp = tid >> 3, sub = tid & 7;
    int d = blockIdx.x * 32 + grp;  // 3125 blocks * 32 = 100000 exact

    const uint4* U = (const uint4*)g_uh;  // 8 uint4 (8 halves each) per row
    uint4 raw = U[(size_t)d * 8 + sub];   // self-loop term
    __half2 ae[4], ao[4];
    ae[0] = *(__half2*)&raw.x; ae[1] = *(__half2*)&raw.y;
    ae[2] = *(__half2*)&raw.z; ae[3] = *(__half2*)&raw.w;
    #pragma unroll
    for (int q = 0; q < 4; q++) ao[q] = __float2half2_rn(0.f);

    int n = g_cnt[d];
    const int* bkt = &g_csr[d << BKT_SHIFT];
    int e = 0;
    #pragma unroll 2
    for (; e + 1 < n; e += 2) {
        int s0 = bkt[e], s1 = bkt[e + 1];
        uint4 r0 = U[(size_t)s0 * 8 + sub];
        uint4 r1 = U[(size_t)s1 * 8 + sub];
        ae[0] = __hadd2(ae[0], *(__half2*)&r0.x);
        ae[1] = __hadd2(ae[1], *(__half2*)&r0.y);
        ae[2] = __hadd2(ae[2], *(__half2*)&r0.z);
        ae[3] = __hadd2(ae[3], *(__half2*)&r0.w);
        ao[0] = __hadd2(ao[0], *(__half2*)&r1.x);
        ao[1] = __hadd2(ao[1], *(__half2*)&r1.y);
        ao[2] = __hadd2(ao[2], *(__half2*)&r1.z);
        ao[3] = __hadd2(ao[3], *(__half2*)&r1.w);
    }
    if (e < n) {
        uint4 r0 = U[(size_t)bkt[e] * 8 + sub];
        ao[0] = __hadd2(ao[0], *(__half2*)&r0.x);
        ao[1] = __hadd2(ao[1], *(__half2*)&r0.y);
        ao[2] = __hadd2(ao[2], *(__half2*)&r0.z);
        ao[3] = __hadd2(ao[3], *(__half2*)&r0.w);
    }

    float sc = rsqrtf((float)n + 1.0f);
    float4 b0 = ((const float4*)b)[sub * 2];
    float4 b1 = ((const float4*)b)[sub * 2 + 1];
    float o[8];
    {
        float2 fe, fo;
        fe = __half22float2(ae[0]); fo = __half22float2(ao[0]);
        o[0] = fmaxf(sc * (fe.x + fo.x) + b0.x, 0.f);
        o[1] = fmaxf(sc * (fe.y + fo.y) + b0.y, 0.f);
        fe = __half22float2(ae[1]); fo = __half22float2(ao[1]);
        o[2] = fmaxf(sc * (fe.x + fo.x) + b0.z, 0.f);
        o[3] = fmaxf(sc * (fe.y + fo.y) + b0.w, 0.f);
        fe = __half22float2(ae[2]); fo = __half22float2(ao[2]);
        o[4] = fmaxf(sc * (fe.x + fo.x) + b1.x, 0.f);
        o[5] = fmaxf(sc * (fe.y + fo.y) + b1.y, 0.f);
        fe = __half22float2(ae[3]); fo = __half22float2(ao[3]);
        o[6] = fmaxf(sc * (fe.x + fo.x) + b1.z, 0.f);
        o[7] = fmaxf(sc * (fe.y + fo.y) + b1.w, 0.f);
    }

    if (!FUSE_DOT) {
        __half2 p0 = __floats2half2_rn(o[0], o[1]);
        __half2 p1 = __floats2half2_rn(o[2], o[3]);
        __half2 p2 = __floats2half2_rn(o[4], o[5]);
        __half2 p3 = __floats2half2_rn(o[6], o[7]);
        *(uint4*)&g_h16[(size_t)d * 64 + sub * 8] =
            make_uint4(*(uint32_t*)&p0, *(uint32_t*)&p1,
                       *(uint32_t*)&p2, *(uint32_t*)&p3);
    } else {
        float4 w0 = ((const float4*)W3)[sub * 2];
        float4 w1 = ((const float4*)W3)[sub * 2 + 1];
        float dot = o[0] * w0.x + o[1] * w0.y + o[2] * w0.z + o[3] * w0.w +
                    o[4] * w1.x + o[5] * w1.y + o[6] * w1.z + o[7] * w1.w;
        #pragma unroll
        for (int off = 4; off; off >>= 1) dot += __shfl_xor_sync(0xffffffffu, dot, off);
        if (sub == 0) g_u3[d] = dot * sc;
    }
    GDC_LAUNCH();
}

// ---------------- final: out = sigmoid(dis*(sum u3 + u3[d]) + b3) -------------
// Also re-zeroes g_cnt for the next graph replay (invariant: zero on entry).
__global__ void final_k(const float* __restrict__ b3, float* __restrict__ out) {
    GDC_WAIT();
    int d = blockIdx.x * blockDim.x + threadIdx.x;
    if (d < NN) {
        int n = g_cnt[d];
        const int* bkt = &g_csr[d << BKT_SHIFT];
        float s = g_u3[d];
        #pragma unroll 4
        for (int e = 0; e < n; e++) s += g_u3[bkt[e]];
        float z = rsqrtf((float)n + 1.0f) * s + b3[0];
        out[d] = 1.0f / (1.0f + expf(-z));
        g_cnt[d] = 0;
    }
}

// ---------------- launch -------------------------------------------------------
template <typename F, typename... A>
static inline void pdl(F* f, dim3 grid, dim3 blk, size_t smem, A... args) {
    cudaLaunchConfig_t cfg = {};
    cfg.gridDim = grid;
    cfg.blockDim = blk;
    cfg.dynamicSmemBytes = smem;
    cfg.stream = 0;
    cudaLaunchAttribute at[1];
    at[0].id = cudaLaunchAttributeProgrammaticStreamSerialization;
    at[0].val.programmaticStreamSerializationAllowed = 1;
    cfg.attrs = at;
    cfg.numAttrs = 1;
    cudaLaunchKernelEx(&cfg, f, args...);
}

extern "C" void kernel_launch(void* const* d_in, const int* in_sizes, int n_in,
                              void* d_out, int out_size) {
    const float* x  = (const float*)d_in[0];
    const float* W1 = (const float*)d_in[1];
    const float* b1 = (const float*)d_in[2];
    const float* W2 = (const float*)d_in[3];
    const float* b2 = (const float*)d_in[4];
    const float* W3 = (const float*)d_in[5];
    const float* b3 = (const float*)d_in[6];
    const void*  ei = d_in[7];
    float* out = (float*)d_out;

    const int SMEM = 1024 + 32768 + 8192;  // pad + A + B = 41984
    cudaFuncSetAttribute(gemm_mma<2, false>, cudaFuncAttributeMaxDynamicSharedMemorySize, SMEM);
    cudaFuncSetAttribute(gemm_mma<1, true>,  cudaFuncAttributeMaxDynamicSharedMemorySize, SMEM);

    const int NBLK = (NN + 255) / 256;  // 391

    // structure: one kernel (fixed-stride buckets, no scan)
    pdl(bucket_k, dim3((NE + 255) / 256), dim3(256), 0, ei);

    // layer 1
    pdl(gemm_mma<2, false>, dim3(NBLK), dim3(256), SMEM, x, W1);
    pdl(agg_relu<false>, dim3((NN + 31) / 32, 1, 1), dim3(256), 0, b1, (const float*)nullptr);
    // layer 2 (+ fused layer-3 dot)
    pdl(gemm_mma<1, true>, dim3(NBLK), dim3(256), SMEM, (const float*)nullptr, W2);
    pdl(agg_relu<true>, dim3((NN + 31) / 32, 1, 1), dim3(256), 0, b2, W3);
    // final
    pdl(final_k, dim3((NN + 255) / 256), dim3(256), 0, b3, out);
}